// round 1
// baseline (speedup 1.0000x reference)
#include <cuda_runtime.h>

#define NWARPS  2432
#define NBLOCKS 608
#define BLOCK   128
#define WARM    32

typedef unsigned long long u64;

__device__ __forceinline__ u64 pk2(float a, float b) {
    u64 r; asm("mov.b64 %0, {%1,%2};" : "=l"(r) : "f"(a), "f"(b)); return r;
}
__device__ __forceinline__ void unpk2(float& a, float& b, u64 r) {
    asm("mov.b64 {%0,%1}, %2;" : "=f"(a), "=f"(b) : "l"(r));
}
__device__ __forceinline__ u64 fma2(u64 a, u64 b, u64 c) {
    u64 d; asm("fma.rn.f32x2 %0, %1, %2, %3;" : "=l"(d) : "l"(a), "l"(b), "l"(c)); return d;
}
__device__ __forceinline__ u64 add2(u64 a, u64 b) {
    u64 d; asm("add.rn.f32x2 %0, %1, %2;" : "=l"(d) : "l"(a), "l"(b)); return d;
}
__device__ __forceinline__ float frcp(float x) {
    float r; asm("rcp.approx.f32 %0, %1;" : "=f"(r) : "f"(x)); return r;
}

__global__ void __launch_bounds__(BLOCK, 4) rnn_scan_kernel(
    const float* __restrict__ x, const float* __restrict__ weight,
    const float* __restrict__ weight_y, const float* __restrict__ bias,
    const float* __restrict__ weight_ln, const float* __restrict__ bias_ln,
    float* __restrict__ out, int B, int L)
{
    __shared__ __align__(16) float xs[BLOCK / 32][32][32];

    const int w    = threadIdx.x >> 5;
    const int lane = threadIdx.x & 31;
    const int wid  = blockIdx.x * (BLOCK / 32) + w;
    const int start = wid * L;
    if (start >= B) return;
    const int tstop = min(start + L, B);
    const int t0    = (wid == 0) ? 0 : start - WARM;   // contraction warmup

    // Per-lane weights: lane owns hidden columns (2*lane, 2*lane+1) as f32x2 pairs
    u64 w2[16];
#pragma unroll
    for (int i = 0; i < 16; i++) {
        float2 t = *(const float2*)(weight + i * 64 + 2 * lane);
        w2[i] = pk2(t.x, t.y);
    }
    float2 wyt = *(const float2*)(weight_y + 2 * lane);
    const u64 wy2 = pk2(wyt.x, wyt.y);
    float2 wlt = *(const float2*)(weight_ln + 2 * lane);
    const float wl0 = wlt.x, wl1 = wlt.y;
    const float bln = bias_ln[0];
    const u64 bias2 = pk2(bias[0], bias[0]);
    const u64 zero2 = pk2(0.f, 0.f);

    u64 s2  = zero2;   // sigmoid state pair (exact zero init for chunk 0)
    u64 y2v = zero2;   // pre-activation pair of most recent step

    const int jrow = lane >> 2;
    const int q    = lane & 3;
    float4 pf[4];

    auto loadregs = [&](int tb) {
#pragma unroll
        for (int r = 0; r < 4; r++) {
            int t = tb + r * 8 + jrow;
            if (t < B) pf[r] = *(const float4*)(x + (size_t)t * 64 + q * 4);
            else       pf[r] = make_float4(0.f, 0.f, 0.f, 0.f);
        }
    };
    auto stsregs = [&]() {
#pragma unroll
        for (int r = 0; r < 4; r++) {
            float4* dst = (float4*)&xs[w][r * 8 + jrow][q * 8];
            dst[0] = make_float4(pf[r].x, pf[r].x, pf[r].y, pf[r].y);  // duplicated pairs
            dst[1] = make_float4(pf[r].z, pf[r].z, pf[r].w, pf[r].w);
        }
    };

    loadregs(t0);  // prefetch first tile

    for (int tb = t0; tb < tstop; tb += 32) {
        stsregs();
        __syncwarp();
        if (tb + 32 < tstop) loadregs(tb + 32);   // prefetch next tile into regs

        const int n = min(32, tstop - tb);
        float v = 0.f;                            // elected output for step (tb+lane)

        auto step = [&](int j) {
            const ulonglong2* xr = (const ulonglong2*)(&xs[w][j][0]);
            u64 cA = bias2, cB = zero2;           // two chains to halve RAW latency
#pragma unroll
            for (int i = 0; i < 4; i++) {
                ulonglong2 qa = xr[2 * i];
                ulonglong2 qb = xr[2 * i + 1];
                cA = fma2(qa.x, w2[4 * i + 0], cA);
                cB = fma2(qa.y, w2[4 * i + 1], cB);
                cA = fma2(qb.x, w2[4 * i + 2], cA);
                cB = fma2(qb.y, w2[4 * i + 3], cB);
            }
            y2v = fma2(wy2, s2, add2(cA, cB));
            float y0, y1; unpk2(y0, y1, y2v);
            float e0 = exp2f(y0 * -1.4426950408889634f);   // FMUL + MUFU.EX2
            float e1 = exp2f(y1 * -1.4426950408889634f);
            float s0 = frcp(1.f + e0);                     // FADD + MUFU.RCP
            float s1 = frcp(1.f + e1);
            s2 = pk2(s0, s1);
            float p = fmaf(s1, wl1, s0 * wl0);
            p += __shfl_xor_sync(0xffffffffu, p, 16);
            p += __shfl_xor_sync(0xffffffffu, p, 8);
            p += __shfl_xor_sync(0xffffffffu, p, 4);
            p += __shfl_xor_sync(0xffffffffu, p, 2);
            p += __shfl_xor_sync(0xffffffffu, p, 1);
            if (j == lane) v = p;                 // elect: lane j keeps step tb+j
        };

        if (n == 32) {
#pragma unroll
            for (int j = 0; j < 32; j++) step(j);
        } else {
            for (int j = 0; j < n; j++) step(j);
        }

        int t = tb + lane;
        if (lane < n && t >= start) out[t] = v + bln;   // coalesced 128B store / 32 steps
        __syncwarp();
    }

    // Unique last chunk (start < B <= start+L) writes final carries
    if (start + L >= B) {
        float yl0, yl1, sl0, sl1;
        unpk2(yl0, yl1, y2v);
        unpk2(sl0, sl1, s2);
        *(float2*)(out + B + 2 * lane)      = make_float2(yl0, yl1);  // y_h final
        *(float2*)(out + B + 64 + 2 * lane) = make_float2(sl0, sl1);  // y_hs final
    }
}

extern "C" void kernel_launch(void* const* d_in, const int* in_sizes, int n_in,
                              void* d_out, int out_size)
{
    const float* x   = (const float*)d_in[0];
    const float* wt  = (const float*)d_in[1];
    const float* wy  = (const float*)d_in[2];
    const float* b   = (const float*)d_in[3];
    const float* wln = (const float*)d_in[4];
    const float* bln = (const float*)d_in[5];
    float* out = (float*)d_out;

    const int B = in_sizes[0] / 64;                 // x is (B, T=4, I=16); row stride 64
    const int L = (B + NWARPS - 1) / NWARPS;        // steps per chunk

    rnn_scan_kernel<<<NBLOCKS, BLOCK>>>(x, wt, wy, b, wln, bln, out, B, L);
}

// round 2
// speedup vs baseline: 1.7220x; 1.7220x over previous
#include <cuda_runtime.h>

#define BLOCK   128
#define WPB     4
#define NBLOCKS 912
#define NWARPS  (NBLOCKS * WPB)
#define WARM    16
#define XP      36   // padded smem row stride (floats): 36*4=144B, 16B-aligned, 9 coprime 32

typedef unsigned long long u64;

__device__ __forceinline__ u64 pk2(float a, float b) {
    u64 r; asm("mov.b64 %0, {%1,%2};" : "=l"(r) : "f"(a), "f"(b)); return r;
}
__device__ __forceinline__ void unpk2(float& a, float& b, u64 r) {
    asm("mov.b64 {%0,%1}, %2;" : "=f"(a), "=f"(b) : "l"(r));
}
__device__ __forceinline__ u64 fma2(u64 a, u64 b, u64 c) {
    u64 d; asm("fma.rn.f32x2 %0, %1, %2, %3;" : "=l"(d) : "l"(a), "l"(b), "l"(c)); return d;
}
__device__ __forceinline__ u64 add2(u64 a, u64 b) {
    u64 d; asm("add.rn.f32x2 %0, %1, %2;" : "=l"(d) : "l"(a), "l"(b)); return d;
}
__device__ __forceinline__ float frcp(float x) {
    float r; asm("rcp.approx.f32 %0, %1;" : "=f"(r) : "f"(x)); return r;
}

__global__ void __launch_bounds__(BLOCK, 6) rnn_scan_kernel(
    const float* __restrict__ x, const float* __restrict__ weight,
    const float* __restrict__ weight_y, const float* __restrict__ bias,
    const float* __restrict__ weight_ln, const float* __restrict__ bias_ln,
    float* __restrict__ out, int B, int L)
{
    __shared__ __align__(16) float xs[WPB][32][XP];   // duplicated x pairs, padded rows
    __shared__ __align__(16) float ps[WPB][32][XP];   // per-step per-lane output partials

    const int w    = threadIdx.x >> 5;
    const int lane = threadIdx.x & 31;
    const int wid  = blockIdx.x * WPB + w;
    const int start = wid * L;
    if (start >= B) return;
    const int tstop = min(start + L, B);
    const int t0    = (wid == 0) ? 0 : start - WARM;   // contraction warmup (<=0.25^16 error)

    // Lane owns hidden columns (2*lane, 2*lane+1) as f32x2 pairs
    u64 w2[16];
#pragma unroll
    for (int i = 0; i < 16; i++) {
        float2 t = *(const float2*)(weight + i * 64 + 2 * lane);
        w2[i] = pk2(t.x, t.y);
    }
    float2 wyt = *(const float2*)(weight_y + 2 * lane);
    const u64 wy2 = pk2(wyt.x, wyt.y);
    float2 wlt = *(const float2*)(weight_ln + 2 * lane);
    const float wl0 = wlt.x, wl1 = wlt.y;
    const float bln = bias_ln[0];
    const u64 bias2 = pk2(bias[0], bias[0]);
    const u64 zero2 = pk2(0.f, 0.f);

    u64 s2  = zero2;   // sigmoid state pair
    u64 y2v = zero2;   // last pre-activation pair

    const int jr = lane >> 2;   // row group 0..7
    const int q  = lane & 3;    // quarter 0..3
    float4 pf[4];

    auto loadregs = [&](int tb) {
#pragma unroll
        for (int r = 0; r < 4; r++) {
            int t = tb + r * 8 + jr;
            if (t < B) pf[r] = *(const float4*)(x + (size_t)t * 64 + q * 4);
            else       pf[r] = make_float4(0.f, 0.f, 0.f, 0.f);
        }
    };
    auto stsregs = [&]() {
#pragma unroll
        for (int r = 0; r < 4; r++) {
            float* row = &xs[w][r * 8 + jr][q * 8];
            ((float4*)row)[0] = make_float4(pf[r].x, pf[r].x, pf[r].y, pf[r].y);
            ((float4*)row)[1] = make_float4(pf[r].z, pf[r].z, pf[r].w, pf[r].w);
        }
    };

    auto step = [&](int j) {
        const ulonglong2* xr = (const ulonglong2*)(&xs[w][j][0]);   // broadcast reads
        u64 cA = bias2, cB = zero2;           // two chains halve RAW latency
#pragma unroll
        for (int i = 0; i < 4; i++) {
            ulonglong2 qa = xr[2 * i];
            ulonglong2 qb = xr[2 * i + 1];
            cA = fma2(qa.x, w2[4 * i + 0], cA);
            cB = fma2(qa.y, w2[4 * i + 1], cB);
            cA = fma2(qb.x, w2[4 * i + 2], cA);
            cB = fma2(qb.y, w2[4 * i + 3], cB);
        }
        y2v = fma2(wy2, s2, add2(cA, cB));
        float y0, y1; unpk2(y0, y1, y2v);
        float e0 = exp2f(y0 * -1.4426950408889634f);   // FMUL + MUFU.EX2
        float e1 = exp2f(y1 * -1.4426950408889634f);
        float s0 = frcp(1.f + e0);                     // FADD + MUFU.RCP
        float s1 = frcp(1.f + e1);
        s2 = pk2(s0, s1);
        ps[w][j][lane] = fmaf(s1, wl1, s0 * wl0);      // conflict-free STS.32
    };

    loadregs(t0);  // prefetch first tile

    for (int tb = t0; tb < tstop; tb += 32) {
        stsregs();
        __syncwarp();
        if (tb + 32 < tstop) loadregs(tb + 32);   // prefetch next tile into regs

        const int n = min(32, tstop - tb);
        if (n == 32) {
#pragma unroll
            for (int j = 0; j < 32; j++) step(j);
        } else {
            for (int j = 0; j < n; j++) step(j);
        }
        __syncwarp();

        // Lane l reduces step (tb+l): sums row l of ps (32 partials)
        int t = tb + lane;
        if (lane < n && t >= start) {
            const float4* pr = (const float4*)(&ps[w][lane][0]);
            float4 a0 = pr[0], a1 = pr[1], a2 = pr[2], a3 = pr[3];
            float4 a4 = pr[4], a5 = pr[5], a6 = pr[6], a7 = pr[7];
            float r0 = ((a0.x + a0.y) + (a0.z + a0.w)) + ((a1.x + a1.y) + (a1.z + a1.w));
            float r1 = ((a2.x + a2.y) + (a2.z + a2.w)) + ((a3.x + a3.y) + (a3.z + a3.w));
            float r2 = ((a4.x + a4.y) + (a4.z + a4.w)) + ((a5.x + a5.y) + (a5.z + a5.w));
            float r3 = ((a6.x + a6.y) + (a6.z + a6.w)) + ((a7.x + a7.y) + (a7.z + a7.w));
            out[t] = bln + ((r0 + r1) + (r2 + r3));    // coalesced 128B store / 32 steps
        }
        __syncwarp();
    }

    // Unique last chunk writes final carries
    if (start + L >= B) {
        float yl0, yl1, sl0, sl1;
        unpk2(yl0, yl1, y2v);
        unpk2(sl0, sl1, s2);
        *(float2*)(out + B + 2 * lane)      = make_float2(yl0, yl1);  // y_h final
        *(float2*)(out + B + 64 + 2 * lane) = make_float2(sl0, sl1);  // y_hs final
    }
}

extern "C" void kernel_launch(void* const* d_in, const int* in_sizes, int n_in,
                              void* d_out, int out_size)
{
    const float* x   = (const float*)d_in[0];
    const float* wt  = (const float*)d_in[1];
    const float* wy  = (const float*)d_in[2];
    const float* b   = (const float*)d_in[3];
    const float* wln = (const float*)d_in[4];
    const float* bln = (const float*)d_in[5];
    float* out = (float*)d_out;

    const int B = in_sizes[0] / 64;                 // x is (B, T=4, I=16); row stride 64
    const int L = (B + NWARPS - 1) / NWARPS;        // steps per chunk

    rnn_scan_kernel<<<NBLOCKS, BLOCK>>>(x, wt, wy, b, wln, bln, out, B, L);
}

// round 3
// speedup vs baseline: 2.0761x; 1.2056x over previous
#include <cuda_runtime.h>

#define BLOCK   128
#define WPB     4
#define NSM     152
#define OCC     5
#define NBLOCKS (NSM * OCC)
#define NWARPS  (NBLOCKS * WPB)
#define WARM    12
#define XSP     20   // xs row stride (floats): 80B, keeps rows 16B-aligned
#define PSP     36   // ps row stride (floats): conflict-free reduce

typedef unsigned long long u64;

__device__ __forceinline__ u64 pk2(float a, float b) {
    u64 r; asm("mov.b64 %0, {%1,%2};" : "=l"(r) : "f"(a), "f"(b)); return r;
}
__device__ __forceinline__ void unpk2(float& a, float& b, u64 r) {
    asm("mov.b64 {%0,%1}, %2;" : "=f"(a), "=f"(b) : "l"(r));
}
__device__ __forceinline__ u64 fma2(u64 a, u64 b, u64 c) {
    u64 d; asm("fma.rn.f32x2 %0, %1, %2, %3;" : "=l"(d) : "l"(a), "l"(b), "l"(c)); return d;
}
__device__ __forceinline__ float fex2(float x) {
    float r; asm("ex2.approx.f32 %0, %1;" : "=f"(r) : "f"(x)); return r;
}
__device__ __forceinline__ float frcp(float x) {
    float r; asm("rcp.approx.f32 %0, %1;" : "=f"(r) : "f"(x)); return r;
}

__global__ void __launch_bounds__(BLOCK, OCC) rnn_scan_kernel(
    const float* __restrict__ x, const float* __restrict__ weight,
    const float* __restrict__ weight_y, const float* __restrict__ bias,
    const float* __restrict__ weight_ln, const float* __restrict__ bias_ln,
    float* __restrict__ out, int B, int L)
{
    __shared__ __align__(16) float xs[WPB][32][XSP];   // raw x rows (16 floats)
    __shared__ __align__(16) float ps[WPB][32][PSP];   // per-step per-lane partials

    const int w    = threadIdx.x >> 5;
    const int lane = threadIdx.x & 31;
    const int wid  = blockIdx.x * WPB + w;
    const int start = wid * L;
    if (start >= B) return;
    const int tstop = min(start + L, B);
    const int t0    = (wid == 0) ? 0 : start - WARM;   // contraction warmup

    const float SC = -1.4426950408889634f;  // -log2(e): fold into weights so z = -y*log2e

    // Lane owns hidden (h0,h1) = (2*lane, 2*lane+1).
    // Crossed-half chains so the x multiplier is the NATURAL pair {x_2k, x_2k+1}:
    //   chain0 weights {W[2k][h0], W[2k+1][h1]}, chain1 weights {W[2k][h1], W[2k+1][h0]}
    //   z[h0] = c0.lo + c1.hi ; z[h1] = c1.lo + c0.hi
    const int h0 = 2 * lane, h1 = 2 * lane + 1;
    u64 w0k[8], w1k[8];
#pragma unroll
    for (int k = 0; k < 8; k++) {
        const float* r0 = weight + (2 * k) * 64;
        const float* r1 = weight + (2 * k + 1) * 64;
        w0k[k] = pk2(SC * r0[h0], SC * r1[h1]);
        w1k[k] = pk2(SC * r0[h1], SC * r1[h0]);
    }
    const float wyz0 = SC * weight_y[h0];
    const float wyz1 = SC * weight_y[h1];
    const float wl0  = weight_ln[h0];
    const float wl1  = weight_ln[h1];
    const float bln  = bias_ln[0];
    const float bz   = SC * bias[0];
    const u64 binit  = pk2(bz, 0.f);

    float s0 = 0.f, s1 = 0.f;      // sigmoid state (exact zero init for chunk 0)
    float z0 = 0.f, z1 = 0.f;      // last scaled pre-activation

    const int jr = lane >> 2;      // row group 0..7
    const int q  = lane & 3;       // quarter 0..3
    float4 pf[4];

    auto loadregs = [&](int tb) {
#pragma unroll
        for (int r = 0; r < 4; r++) {
            int t = tb + r * 8 + jr;
            if (t < B) pf[r] = *(const float4*)(x + (size_t)t * 64 + q * 4);
            else       pf[r] = make_float4(0.f, 0.f, 0.f, 0.f);
        }
    };
    auto stsregs = [&]() {
#pragma unroll
        for (int r = 0; r < 4; r++)
            *(float4*)&xs[w][r * 8 + jr][q * 4] = pf[r];   // unduplicated: 1 STS.128
    };

    auto step = [&](int j) {
        const ulonglong2* xr = (const ulonglong2*)(&xs[w][j][0]);  // 4 broadcast LDS.128
        ulonglong2 qa = xr[0], qb = xr[1], qc = xr[2], qd = xr[3];
        u64 c0 = binit, c1 = binit;
        c0 = fma2(qa.x, w0k[0], c0);  c1 = fma2(qa.x, w1k[0], c1);
        c0 = fma2(qa.y, w0k[1], c0);  c1 = fma2(qa.y, w1k[1], c1);
        c0 = fma2(qb.x, w0k[2], c0);  c1 = fma2(qb.x, w1k[2], c1);
        c0 = fma2(qb.y, w0k[3], c0);  c1 = fma2(qb.y, w1k[3], c1);
        c0 = fma2(qc.x, w0k[4], c0);  c1 = fma2(qc.x, w1k[4], c1);
        c0 = fma2(qc.y, w0k[5], c0);  c1 = fma2(qc.y, w1k[5], c1);
        c0 = fma2(qd.x, w0k[6], c0);  c1 = fma2(qd.x, w1k[6], c1);
        c0 = fma2(qd.y, w0k[7], c0);  c1 = fma2(qd.y, w1k[7], c1);
        float a0, b0, a1, b1;
        unpk2(a0, b0, c0);            // register aliasing, no real MOVs
        unpk2(a1, b1, c1);
        float zz0 = a0 + b1;          // bias included once via binit.lo of each chain
        float zz1 = a1 + b0;
        z0 = fmaf(wyz0, s0, zz0);     // recurrence (scaled)
        z1 = fmaf(wyz1, s1, zz1);
        float e0 = fex2(z0);          // sigma(y) = 1/(1+2^z)
        float e1 = fex2(z1);
        s0 = frcp(1.f + e0);
        s1 = frcp(1.f + e1);
        ps[w][j][lane] = fmaf(s1, wl1, s0 * wl0);   // conflict-free STS.32
    };

    loadregs(t0);  // prefetch first tile

    for (int tb = t0; tb < tstop; tb += 32) {
        stsregs();
        __syncwarp();
        if (tb + 32 < tstop) loadregs(tb + 32);   // prefetch next tile into regs

        const int n = min(32, tstop - tb);
        if (n == 32) {
#pragma unroll
            for (int j = 0; j < 32; j++) step(j);
        } else {
            for (int j = 0; j < n; j++) step(j);
        }
        __syncwarp();

        // Lane l reduces step (tb+l): sums row l of ps (32 partials)
        int t = tb + lane;
        if (lane < n && t >= start) {
            const float4* pr = (const float4*)(&ps[w][lane][0]);
            float4 a0 = pr[0], a1 = pr[1], a2 = pr[2], a3 = pr[3];
            float4 a4 = pr[4], a5 = pr[5], a6 = pr[6], a7 = pr[7];
            float r0 = ((a0.x + a0.y) + (a0.z + a0.w)) + ((a1.x + a1.y) + (a1.z + a1.w));
            float r1 = ((a2.x + a2.y) + (a2.z + a2.w)) + ((a3.x + a3.y) + (a3.z + a3.w));
            float r2 = ((a4.x + a4.y) + (a4.z + a4.w)) + ((a5.x + a5.y) + (a5.z + a5.w));
            float r3 = ((a6.x + a6.y) + (a6.z + a6.w)) + ((a7.x + a7.y) + (a7.z + a7.w));
            out[t] = bln + ((r0 + r1) + (r2 + r3));   // coalesced 128B store / 32 steps
        }
        __syncwarp();
    }

    // Unique last chunk writes final carries. y = z * (-ln2) undoes the -log2e fold.
    if (start + L >= B) {
        const float NL2 = -0.6931471805599453f;
        *(float2*)(out + B + 2 * lane)      = make_float2(z0 * NL2, z1 * NL2);  // y_h
        *(float2*)(out + B + 64 + 2 * lane) = make_float2(s0, s1);              // y_hs
    }
}

extern "C" void kernel_launch(void* const* d_in, const int* in_sizes, int n_in,
                              void* d_out, int out_size)
{
    const float* x   = (const float*)d_in[0];
    const float* wt  = (const float*)d_in[1];
    const float* wy  = (const float*)d_in[2];
    const float* b   = (const float*)d_in[3];
    const float* wln = (const float*)d_in[4];
    const float* bln = (const float*)d_in[5];
    float* out = (float*)d_out;

    const int B = in_sizes[0] / 64;                 // x is (B, T=4, I=16); row stride 64
    const int L = (B + NWARPS - 1) / NWARPS;        // steps per chunk

    rnn_scan_kernel<<<NBLOCKS, BLOCK>>>(x, wt, wy, b, wln, bln, out, B, L);
}